// round 6
// baseline (speedup 1.0000x reference)
#include <cuda_runtime.h>
#include <cuda_bf16.h>
#include <cstdint>

#define N_NODES 100000
#define N_EDGES_MAX 3200000
#define D 128

// ---------------------------------------------------------------------------
// Device scratch (static; no runtime alloc)
// ---------------------------------------------------------------------------
__device__ int g_cnt[N_NODES];
__device__ int g_off[N_NODES + 1];
__device__ int g_cur[N_NODES];
__device__ int g_srcs[N_EDGES_MAX];
__device__ int g_blksum[128];
__device__ int g_blkoff[128];

// Transposed, padded, split-bf16 weight images: Wt[n][k], row stride 136 elems.
#define ST_ELEM 136
#define ST_W    68
__device__ __align__(16) uint16_t g_w1hi[D * ST_ELEM];
__device__ __align__(16) uint16_t g_w1lo[D * ST_ELEM];
__device__ __align__(16) uint16_t g_w2hi[D * ST_ELEM];
__device__ __align__(16) uint16_t g_w2lo[D * ST_ELEM];

#define SCAN_BLK 1024
#define N_SCAN_BLKS ((N_NODES + SCAN_BLK - 1) / SCAN_BLK)   // 98

// ---------------------------------------------------------------------------
// helpers
// ---------------------------------------------------------------------------
__device__ __forceinline__ void mma_bf16(float* c, const uint32_t* a, const uint32_t* b) {
    asm volatile(
        "mma.sync.aligned.m16n8k16.row.col.f32.bf16.bf16.f32 "
        "{%0,%1,%2,%3}, {%4,%5,%6,%7}, {%8,%9}, {%0,%1,%2,%3};"
        : "+f"(c[0]), "+f"(c[1]), "+f"(c[2]), "+f"(c[3])
        : "r"(a[0]), "r"(a[1]), "r"(a[2]), "r"(a[3]), "r"(b[0]), "r"(b[1]));
}

__device__ __forceinline__ void split_pack(float x, float y, uint32_t& hp, uint32_t& lp) {
    __nv_bfloat16 xh = __float2bfloat16_rn(x);
    __nv_bfloat16 yh = __float2bfloat16_rn(y);
    __nv_bfloat16 xl = __float2bfloat16_rn(x - __bfloat162float(xh));
    __nv_bfloat16 yl = __float2bfloat16_rn(y - __bfloat162float(yh));
    hp = (uint32_t)__bfloat16_as_ushort(xh) | ((uint32_t)__bfloat16_as_ushort(yh) << 16);
    lp = (uint32_t)__bfloat16_as_ushort(xl) | ((uint32_t)__bfloat16_as_ushort(yl) << 16);
}

// ---------------------------------------------------------------------------
// Binning pipeline
// ---------------------------------------------------------------------------
__global__ void zero_cnt_kernel() {
    int i = blockIdx.x * blockDim.x + threadIdx.x;
    if (i < N_NODES) g_cnt[i] = 0;
}

__global__ void hist_kernel(const int* __restrict__ dst, int n_edges) {
    int i = blockIdx.x * blockDim.x + threadIdx.x;
    if (i < n_edges) atomicAdd(&g_cnt[dst[i]], 1);
}

__global__ void scan_block_kernel() {
    __shared__ int s[SCAN_BLK];
    int t = threadIdx.x;
    int i = blockIdx.x * SCAN_BLK + t;
    s[t] = (i < N_NODES) ? g_cnt[i] : 0;
    __syncthreads();
    for (int off = SCAN_BLK / 2; off > 0; off >>= 1) {
        if (t < off) s[t] += s[t + off];
        __syncthreads();
    }
    if (t == 0) g_blksum[blockIdx.x] = s[0];
}

// parallel exclusive scan of 98 block sums (one block, Hillis-Steele)
__global__ void scan_top_kernel() {
    __shared__ int s[128];
    int t = threadIdx.x;
    int v = (t < N_SCAN_BLKS) ? g_blksum[t] : 0;
    s[t] = v;
    __syncthreads();
#pragma unroll
    for (int off = 1; off < 128; off <<= 1) {
        int x = (t >= off) ? s[t - off] : 0;
        __syncthreads();
        s[t] += x;
        __syncthreads();
    }
    if (t < N_SCAN_BLKS) g_blkoff[t] = s[t] - v;
    if (t == N_SCAN_BLKS - 1) g_off[N_NODES] = s[t];
}

__global__ void scan_final_kernel() {
    __shared__ int s[SCAN_BLK];
    int t = threadIdx.x;
    int i = blockIdx.x * SCAN_BLK + t;
    int v = (i < N_NODES) ? g_cnt[i] : 0;
    s[t] = v;
    __syncthreads();
    for (int off = 1; off < SCAN_BLK; off <<= 1) {
        int x = (t >= off) ? s[t - off] : 0;
        __syncthreads();
        s[t] += x;
        __syncthreads();
    }
    if (i < N_NODES) {
        int excl = s[t] - v + g_blkoff[blockIdx.x];
        g_off[i] = excl;
        g_cur[i] = excl;
    }
}

__global__ void fill_kernel(const int* __restrict__ src,
                            const int* __restrict__ dst, int n_edges) {
    int i = blockIdx.x * blockDim.x + threadIdx.x;
    if (i < n_edges) {
        int pos = atomicAdd(&g_cur[dst[i]], 1);
        g_srcs[pos] = src[i];
    }
}

// ---------------------------------------------------------------------------
// Weight prep: Wt[n][k] = W[k][n], split bf16 hi/lo, stride 136
// ---------------------------------------------------------------------------
__global__ void prep_weights_kernel(const float* __restrict__ W1,
                                    const float* __restrict__ W2) {
    int idx = blockIdx.x * blockDim.x + threadIdx.x;
    if (idx >= D * D) return;
    int k = idx >> 7;
    int n = idx & 127;
    int o = n * ST_ELEM + k;
    {
        float w = W1[idx];
        __nv_bfloat16 h = __float2bfloat16_rn(w);
        __nv_bfloat16 l = __float2bfloat16_rn(w - __bfloat162float(h));
        g_w1hi[o] = __bfloat16_as_ushort(h);
        g_w1lo[o] = __bfloat16_as_ushort(l);
    }
    {
        float w = W2[idx];
        __nv_bfloat16 h = __float2bfloat16_rn(w);
        __nv_bfloat16 l = __float2bfloat16_rn(w - __bfloat162float(h));
        g_w2hi[o] = __bfloat16_as_ushort(h);
        g_w2lo[o] = __bfloat16_as_ushort(l);
    }
}

// ---------------------------------------------------------------------------
// Fused gather + MLP. CTA = 64 node rows, 256 threads / 8 warps, 2 CTAs/SM.
// Phase 1: stage W1; warp-per-row gather -> split-bf16 A tiles in smem.
// Phase 2: HMMA GEMM1 (+b1, relu) -> A tiles; stage W2; GEMM2 (+b2) -> out.
// Warp (wr = wid&3, half = wid>>2): rows [16wr,16wr+16), cols [64half,64half+64)
// ---------------------------------------------------------------------------
#define TILE_M 64
#define A_WORDS (TILE_M * ST_W)     // 4352
#define W_WORDS (128 * ST_W)        // 8704
#define FUSED_SMEM_BYTES ((2 * A_WORDS + 2 * W_WORDS) * 4)   // 104448

__global__ __launch_bounds__(256, 2)
void fused_kernel(const float* __restrict__ feat,
                  const float* __restrict__ epsp,
                  const float* __restrict__ b1,
                  const float* __restrict__ b2,
                  float* __restrict__ out) {
    extern __shared__ uint32_t smem[];
    uint32_t* A_HI = smem;
    uint32_t* A_LO = smem + A_WORDS;
    uint32_t* W_HI = smem + 2 * A_WORDS;
    uint32_t* W_LO = smem + 2 * A_WORDS + W_WORDS;

    const int tid  = threadIdx.x;
    const int wid  = tid >> 5;        // 0..7
    const int lane = tid & 31;
    const int wr   = wid & 3;
    const int half = wid >> 2;
    const int g    = lane >> 2;
    const int t    = lane & 3;
    const int row_base = blockIdx.x * TILE_M;

    // ---- stage W1 ----
    {
        const uint4* s1h = reinterpret_cast<const uint4*>(g_w1hi);
        const uint4* s1l = reinterpret_cast<const uint4*>(g_w1lo);
        uint4* dh = reinterpret_cast<uint4*>(W_HI);
        uint4* dl = reinterpret_cast<uint4*>(W_LO);
        for (int i = tid; i < W_WORDS / 4; i += 256) { dh[i] = s1h[i]; dl[i] = s1l[i]; }
    }

    // ---- fused gather: warp per row, 8 rows per warp ----
    {
        const float e1 = 1.0f + epsp[0];
        const float4* f4 = reinterpret_cast<const float4*>(feat);
        for (int r = wid; r < TILE_M; r += 8) {
            const int v = row_base + r;
            float4 acc = make_float4(0.f, 0.f, 0.f, 0.f);
            if (v < N_NODES) {
                float4 a = f4[(size_t)v * 32 + lane];
                acc = make_float4(a.x * e1, a.y * e1, a.z * e1, a.w * e1);
                const int beg = g_off[v];
                const int end = g_off[v + 1];
                for (int e = beg; e < end; e += 32) {
                    int cnt = end - e;
                    if (cnt > 32) cnt = 32;
                    int s = (lane < cnt) ? g_srcs[e + lane] : 0;
                    if (cnt == 32) {
#pragma unroll
                        for (int j = 0; j < 32; j++) {
                            int sj = __shfl_sync(0xffffffffu, s, j);
                            float4 m = f4[(size_t)sj * 32 + lane];
                            acc.x += m.x; acc.y += m.y; acc.z += m.z; acc.w += m.w;
                        }
                    } else {
                        for (int j = 0; j < cnt; j++) {
                            int sj = __shfl_sync(0xffffffffu, s, j);
                            float4 m = f4[(size_t)sj * 32 + lane];
                            acc.x += m.x; acc.y += m.y; acc.z += m.z; acc.w += m.w;
                        }
                    }
                }
            }
            uint32_t h0, l0, h1, l1;
            split_pack(acc.x, acc.y, h0, l0);
            split_pack(acc.z, acc.w, h1, l1);
            const int word = r * ST_W + lane * 2;
            A_HI[word] = h0; A_HI[word + 1] = h1;
            A_LO[word] = l0; A_LO[word + 1] = l1;
        }
    }
    __syncthreads();

    float acc[8][4];
#pragma unroll
    for (int nt = 0; nt < 8; nt++)
#pragma unroll
        for (int j = 0; j < 4; j++) acc[nt][j] = 0.f;

    const int ar0 = (wr * 16 + g) * ST_W;
    const int ar1 = ar0 + 8 * ST_W;

    // ================= GEMM 1 =================
#pragma unroll
    for (int kc = 0; kc < 8; kc++) {
        const int kw = kc * 8 + t;
        uint32_t ah[4], al[4];
        ah[0] = A_HI[ar0 + kw];     ah[1] = A_HI[ar1 + kw];
        ah[2] = A_HI[ar0 + kw + 4]; ah[3] = A_HI[ar1 + kw + 4];
        al[0] = A_LO[ar0 + kw];     al[1] = A_LO[ar1 + kw];
        al[2] = A_LO[ar0 + kw + 4]; al[3] = A_LO[ar1 + kw + 4];
#pragma unroll
        for (int nt = 0; nt < 8; nt++) {
            const int bb = (half * 64 + nt * 8 + g) * ST_W + kw;
            uint32_t bh[2] = { W_HI[bb], W_HI[bb + 4] };
            uint32_t bl[2] = { W_LO[bb], W_LO[bb + 4] };
            mma_bf16(acc[nt], ah, bh);
            mma_bf16(acc[nt], ah, bl);
            mma_bf16(acc[nt], al, bh);
        }
    }
    __syncthreads();   // all GEMM1 reads done before A/W overwrite

    // ---- epilogue 1: relu(+b1) -> back into A tiles ----
#pragma unroll
    for (int nt = 0; nt < 8; nt++) {
        const int n = half * 64 + nt * 8 + 2 * t;
        const float bx = __ldg(b1 + n);
        const float by = __ldg(b1 + n + 1);
        float x0 = fmaxf(acc[nt][0] + bx, 0.f);
        float y0 = fmaxf(acc[nt][1] + by, 0.f);
        float x1 = fmaxf(acc[nt][2] + bx, 0.f);
        float y1 = fmaxf(acc[nt][3] + by, 0.f);
        uint32_t hp, lp;
        const int word0 = (wr * 16 + g) * ST_W + (n >> 1);
        const int word1 = word0 + 8 * ST_W;
        split_pack(x0, y0, hp, lp);
        A_HI[word0] = hp; A_LO[word0] = lp;
        split_pack(x1, y1, hp, lp);
        A_HI[word1] = hp; A_LO[word1] = lp;
#pragma unroll
        for (int j = 0; j < 4; j++) acc[nt][j] = 0.f;
    }

    // ---- stage W2 ----
    {
        const uint4* s2h = reinterpret_cast<const uint4*>(g_w2hi);
        const uint4* s2l = reinterpret_cast<const uint4*>(g_w2lo);
        uint4* dh = reinterpret_cast<uint4*>(W_HI);
        uint4* dl = reinterpret_cast<uint4*>(W_LO);
        for (int i = tid; i < W_WORDS / 4; i += 256) { dh[i] = s2h[i]; dl[i] = s2l[i]; }
    }
    __syncthreads();

    // ================= GEMM 2 =================
#pragma unroll
    for (int kc = 0; kc < 8; kc++) {
        const int kw = kc * 8 + t;
        uint32_t ah[4], al[4];
        ah[0] = A_HI[ar0 + kw];     ah[1] = A_HI[ar1 + kw];
        ah[2] = A_HI[ar0 + kw + 4]; ah[3] = A_HI[ar1 + kw + 4];
        al[0] = A_LO[ar0 + kw];     al[1] = A_LO[ar1 + kw];
        al[2] = A_LO[ar0 + kw + 4]; al[3] = A_LO[ar1 + kw + 4];
#pragma unroll
        for (int nt = 0; nt < 8; nt++) {
            const int bb = (half * 64 + nt * 8 + g) * ST_W + kw;
            uint32_t bh[2] = { W_HI[bb], W_HI[bb + 4] };
            uint32_t bl[2] = { W_LO[bb], W_LO[bb + 4] };
            mma_bf16(acc[nt], ah, bh);
            mma_bf16(acc[nt], ah, bl);
            mma_bf16(acc[nt], al, bh);
        }
    }

    // ---- epilogue 2: +b2, store ----
    {
        const int m0 = row_base + wr * 16 + g;
        const int m1 = m0 + 8;
#pragma unroll
        for (int nt = 0; nt < 8; nt++) {
            const int n = half * 64 + nt * 8 + 2 * t;
            const float bx = __ldg(b2 + n);
            const float by = __ldg(b2 + n + 1);
            if (m0 < N_NODES)
                *reinterpret_cast<float2*>(out + (size_t)m0 * D + n) =
                    make_float2(acc[nt][0] + bx, acc[nt][1] + by);
            if (m1 < N_NODES)
                *reinterpret_cast<float2*>(out + (size_t)m1 * D + n) =
                    make_float2(acc[nt][2] + bx, acc[nt][3] + by);
        }
    }
}

// ---------------------------------------------------------------------------
extern "C" void kernel_launch(void* const* d_in, const int* in_sizes, int n_in,
                              void* d_out, int out_size) {
    const float* feat = (const float*)d_in[0];
    const int*   src  = (const int*)d_in[1];
    const int*   dst  = (const int*)d_in[2];
    const float* eps  = (const float*)d_in[3];
    const float* W1   = (const float*)d_in[4];
    const float* b1   = (const float*)d_in[5];
    const float* W2   = (const float*)d_in[6];
    const float* b2   = (const float*)d_in[7];
    float*       out  = (float*)d_out;

    int n_edges = in_sizes[1];
    int eblocks = (n_edges + 255) / 256;

    // ---- binning (CSR by dst) ----
    zero_cnt_kernel<<<(N_NODES + 255) / 256, 256>>>();
    hist_kernel<<<eblocks, 256>>>(dst, n_edges);
    scan_block_kernel<<<N_SCAN_BLKS, SCAN_BLK>>>();
    scan_top_kernel<<<1, 128>>>();
    scan_final_kernel<<<N_SCAN_BLKS, SCAN_BLK>>>();
    fill_kernel<<<eblocks, 256>>>(src, dst, n_edges);

    // ---- weight prep ----
    prep_weights_kernel<<<(D * D + 255) / 256, 256>>>(W1, W2);

    // ---- fused gather + MLP ----
    cudaFuncSetAttribute(fused_kernel, cudaFuncAttributeMaxDynamicSharedMemorySize,
                         FUSED_SMEM_BYTES);
    int blocks = (N_NODES + TILE_M - 1) / TILE_M;
    fused_kernel<<<blocks, 256, FUSED_SMEM_BYTES>>>(feat, eps, b1, b2, out);
}

// round 7
// speedup vs baseline: 1.1388x; 1.1388x over previous
#include <cuda_runtime.h>
#include <cuda_bf16.h>
#include <cstdint>

#define N_NODES 100000
#define N_EDGES_MAX 3200000
#define D 128

// ---------------------------------------------------------------------------
// Device scratch (static; no runtime alloc)
// ---------------------------------------------------------------------------
__device__ float g_neigh[(size_t)N_NODES * D];   // (1+eps)feat + neighbor sum
__device__ int g_cnt[N_NODES];
__device__ int g_off[N_NODES + 1];
__device__ int g_cur[N_NODES];
__device__ int g_srcs[N_EDGES_MAX];
__device__ int g_blksum[128];
__device__ int g_blkoff[128];

// Transposed, padded, split-bf16 weight images: Wt[n][k], row stride 136 elems.
#define ST_ELEM 136
#define ST_W    68
__device__ __align__(16) uint16_t g_w1hi[D * ST_ELEM];
__device__ __align__(16) uint16_t g_w1lo[D * ST_ELEM];
__device__ __align__(16) uint16_t g_w2hi[D * ST_ELEM];
__device__ __align__(16) uint16_t g_w2lo[D * ST_ELEM];

#define SCAN_BLK 1024
#define N_SCAN_BLKS ((N_NODES + SCAN_BLK - 1) / SCAN_BLK)   // 98

// ---------------------------------------------------------------------------
// helpers
// ---------------------------------------------------------------------------
__device__ __forceinline__ void mma_bf16(float* c, const uint32_t* a, const uint32_t* b) {
    asm volatile(
        "mma.sync.aligned.m16n8k16.row.col.f32.bf16.bf16.f32 "
        "{%0,%1,%2,%3}, {%4,%5,%6,%7}, {%8,%9}, {%0,%1,%2,%3};"
        : "+f"(c[0]), "+f"(c[1]), "+f"(c[2]), "+f"(c[3])
        : "r"(a[0]), "r"(a[1]), "r"(a[2]), "r"(a[3]), "r"(b[0]), "r"(b[1]));
}

__device__ __forceinline__ void split_pack(float x, float y, uint32_t& hp, uint32_t& lp) {
    __nv_bfloat16 xh = __float2bfloat16_rn(x);
    __nv_bfloat16 yh = __float2bfloat16_rn(y);
    __nv_bfloat16 xl = __float2bfloat16_rn(x - __bfloat162float(xh));
    __nv_bfloat16 yl = __float2bfloat16_rn(y - __bfloat162float(yh));
    hp = (uint32_t)__bfloat16_as_ushort(xh) | ((uint32_t)__bfloat16_as_ushort(yh) << 16);
    lp = (uint32_t)__bfloat16_as_ushort(xl) | ((uint32_t)__bfloat16_as_ushort(yl) << 16);
}

// ---------------------------------------------------------------------------
// Binning pipeline
// ---------------------------------------------------------------------------
__global__ void zero_cnt_kernel() {
    int i = blockIdx.x * blockDim.x + threadIdx.x;
    if (i < N_NODES) g_cnt[i] = 0;
}

__global__ void hist_kernel(const int* __restrict__ dst, int n_edges) {
    int i = blockIdx.x * blockDim.x + threadIdx.x;
    if (i < n_edges) atomicAdd(&g_cnt[dst[i]], 1);
}

__global__ void scan_block_kernel() {
    __shared__ int s[SCAN_BLK];
    int t = threadIdx.x;
    int i = blockIdx.x * SCAN_BLK + t;
    s[t] = (i < N_NODES) ? g_cnt[i] : 0;
    __syncthreads();
    for (int off = SCAN_BLK / 2; off > 0; off >>= 1) {
        if (t < off) s[t] += s[t + off];
        __syncthreads();
    }
    if (t == 0) g_blksum[blockIdx.x] = s[0];
}

// parallel exclusive scan of 98 block sums (one block, Hillis-Steele)
__global__ void scan_top_kernel() {
    __shared__ int s[128];
    int t = threadIdx.x;
    int v = (t < N_SCAN_BLKS) ? g_blksum[t] : 0;
    s[t] = v;
    __syncthreads();
#pragma unroll
    for (int off = 1; off < 128; off <<= 1) {
        int x = (t >= off) ? s[t - off] : 0;
        __syncthreads();
        s[t] += x;
        __syncthreads();
    }
    if (t < N_SCAN_BLKS) g_blkoff[t] = s[t] - v;
    if (t == N_SCAN_BLKS - 1) g_off[N_NODES] = s[t];
}

__global__ void scan_final_kernel() {
    __shared__ int s[SCAN_BLK];
    int t = threadIdx.x;
    int i = blockIdx.x * SCAN_BLK + t;
    int v = (i < N_NODES) ? g_cnt[i] : 0;
    s[t] = v;
    __syncthreads();
    for (int off = 1; off < SCAN_BLK; off <<= 1) {
        int x = (t >= off) ? s[t - off] : 0;
        __syncthreads();
        s[t] += x;
        __syncthreads();
    }
    if (i < N_NODES) {
        int excl = s[t] - v + g_blkoff[blockIdx.x];
        g_off[i] = excl;
        g_cur[i] = excl;
    }
}

__global__ void fill_kernel(const int* __restrict__ src,
                            const int* __restrict__ dst, int n_edges) {
    int i = blockIdx.x * blockDim.x + threadIdx.x;
    if (i < n_edges) {
        int pos = atomicAdd(&g_cur[dst[i]], 1);
        g_srcs[pos] = src[i];
    }
}

// ---------------------------------------------------------------------------
// Gather-reduce: warp per node. g_neigh[v] = (1+eps)*feat[v] + sum feat[srcs]
// ---------------------------------------------------------------------------
__global__ __launch_bounds__(256)
void gather_kernel(const float* __restrict__ feat,
                   const float* __restrict__ epsp) {
    const int warp = (blockIdx.x * blockDim.x + threadIdx.x) >> 5;
    const int lane = threadIdx.x & 31;
    if (warp >= N_NODES) return;
    const int v = warp;
    const float e1 = 1.0f + epsp[0];

    const float4* f4 = reinterpret_cast<const float4*>(feat);
    float4 a = f4[(size_t)v * 32 + lane];
    float4 acc = make_float4(a.x * e1, a.y * e1, a.z * e1, a.w * e1);

    const int beg = g_off[v];
    const int end = g_off[v + 1];
    for (int e = beg; e < end; e += 32) {
        int cnt = end - e;
        if (cnt > 32) cnt = 32;
        int s = (lane < cnt) ? g_srcs[e + lane] : 0;
        if (cnt == 32) {
#pragma unroll
            for (int j = 0; j < 32; j++) {
                int sj = __shfl_sync(0xffffffffu, s, j);
                float4 m = f4[(size_t)sj * 32 + lane];
                acc.x += m.x; acc.y += m.y; acc.z += m.z; acc.w += m.w;
            }
        } else {
            for (int j = 0; j < cnt; j++) {
                int sj = __shfl_sync(0xffffffffu, s, j);
                float4 m = f4[(size_t)sj * 32 + lane];
                acc.x += m.x; acc.y += m.y; acc.z += m.z; acc.w += m.w;
            }
        }
    }
    reinterpret_cast<float4*>(g_neigh)[(size_t)v * 32 + lane] = acc;
}

// ---------------------------------------------------------------------------
// Weight prep: Wt[n][k] = W[k][n], split bf16 hi/lo, stride 136
// ---------------------------------------------------------------------------
__global__ void prep_weights_kernel(const float* __restrict__ W1,
                                    const float* __restrict__ W2) {
    int idx = blockIdx.x * blockDim.x + threadIdx.x;
    if (idx >= D * D) return;
    int k = idx >> 7;
    int n = idx & 127;
    int o = n * ST_ELEM + k;
    {
        float w = W1[idx];
        __nv_bfloat16 h = __float2bfloat16_rn(w);
        __nv_bfloat16 l = __float2bfloat16_rn(w - __bfloat162float(h));
        g_w1hi[o] = __bfloat16_as_ushort(h);
        g_w1lo[o] = __bfloat16_as_ushort(l);
    }
    {
        float w = W2[idx];
        __nv_bfloat16 h = __float2bfloat16_rn(w);
        __nv_bfloat16 l = __float2bfloat16_rn(w - __bfloat162float(h));
        g_w2hi[o] = __bfloat16_as_ushort(h);
        g_w2lo[o] = __bfloat16_as_ushort(l);
    }
}

// ---------------------------------------------------------------------------
// MLP (HMMA split-bf16). TILE_M=64 rows, 512 threads / 16 warps, 2 CTAs/SM.
// Warp (wr = wid&3, q = wid>>2): rows [16wr,16wr+16), cols [32q,32q+32).
// smem: A_hi|A_lo (64x68 words each) + W_hi|W_lo (128x68 each, W1 then W2).
// ---------------------------------------------------------------------------
#define TILE_M   64
#define A_WORDS  (TILE_M * ST_W)       // 4352
#define W_WORDS  (128 * ST_W)          // 8704
#define MLP_SMEM_BYTES ((2 * A_WORDS + 2 * W_WORDS) * 4)   // 104448

__global__ __launch_bounds__(512, 2)
void mlp_kernel(const float* __restrict__ b1,
                const float* __restrict__ b2,
                float* __restrict__ out) {
    extern __shared__ uint32_t smem[];
    uint32_t* A_HI = smem;
    uint32_t* A_LO = smem + A_WORDS;
    uint32_t* W_HI = smem + 2 * A_WORDS;
    uint32_t* W_LO = smem + 2 * A_WORDS + W_WORDS;

    const int tid  = threadIdx.x;
    const int wid  = tid >> 5;        // 0..15
    const int lane = tid & 31;
    const int wr   = wid & 3;         // row group
    const int q    = wid >> 2;        // col quarter
    const int g    = lane >> 2;
    const int t    = lane & 3;
    const int row_base = blockIdx.x * TILE_M;

    // ---- stage W1 ----
    {
        const uint4* s1h = reinterpret_cast<const uint4*>(g_w1hi);
        const uint4* s1l = reinterpret_cast<const uint4*>(g_w1lo);
        uint4* dh = reinterpret_cast<uint4*>(W_HI);
        uint4* dl = reinterpret_cast<uint4*>(W_LO);
        for (int i = tid; i < W_WORDS / 4; i += 512) { dh[i] = s1h[i]; dl[i] = s1l[i]; }
    }

    // ---- stage A from g_neigh ----
    for (int i = tid; i < TILE_M * 32; i += 512) {
        int r  = i >> 5;
        int c4 = (i & 31) * 4;
        int m  = row_base + r;
        float4 v = (m < N_NODES)
                 ? *reinterpret_cast<const float4*>(g_neigh + (size_t)m * D + c4)
                 : make_float4(0.f, 0.f, 0.f, 0.f);
        uint32_t h0, l0, h1, l1;
        split_pack(v.x, v.y, h0, l0);
        split_pack(v.z, v.w, h1, l1);
        int word = r * ST_W + (c4 >> 1);
        A_HI[word] = h0; A_HI[word + 1] = h1;
        A_LO[word] = l0; A_LO[word + 1] = l1;
    }
    __syncthreads();

    float acc[4][4];
#pragma unroll
    for (int nt = 0; nt < 4; nt++)
#pragma unroll
        for (int j = 0; j < 4; j++) acc[nt][j] = 0.f;

    const int ar0 = (wr * 16 + g) * ST_W;
    const int ar1 = ar0 + 8 * ST_W;

    // ================= GEMM 1 =================
#pragma unroll
    for (int kc = 0; kc < 8; kc++) {
        const int kw = kc * 8 + t;
        uint32_t ah[4], al[4];
        ah[0] = A_HI[ar0 + kw];     ah[1] = A_HI[ar1 + kw];
        ah[2] = A_HI[ar0 + kw + 4]; ah[3] = A_HI[ar1 + kw + 4];
        al[0] = A_LO[ar0 + kw];     al[1] = A_LO[ar1 + kw];
        al[2] = A_LO[ar0 + kw + 4]; al[3] = A_LO[ar1 + kw + 4];
#pragma unroll
        for (int nt = 0; nt < 4; nt++) {
            const int bb = (q * 32 + nt * 8 + g) * ST_W + kw;
            uint32_t bh[2] = { W_HI[bb], W_HI[bb + 4] };
            uint32_t bl[2] = { W_LO[bb], W_LO[bb + 4] };
            mma_bf16(acc[nt], ah, bh);
            mma_bf16(acc[nt], ah, bl);
            mma_bf16(acc[nt], al, bh);
        }
    }
    __syncthreads();   // all GEMM1 reads done before overwrite

    // ---- epilogue 1: relu(+b1) -> back into A tiles ----
#pragma unroll
    for (int nt = 0; nt < 4; nt++) {
        const int n = q * 32 + nt * 8 + 2 * t;
        const float bx = __ldg(b1 + n);
        const float by = __ldg(b1 + n + 1);
        float x0 = fmaxf(acc[nt][0] + bx, 0.f);
        float y0 = fmaxf(acc[nt][1] + by, 0.f);
        float x1 = fmaxf(acc[nt][2] + bx, 0.f);
        float y1 = fmaxf(acc[nt][3] + by, 0.f);
        uint32_t hp, lp;
        const int word0 = (wr * 16 + g) * ST_W + (n >> 1);
        const int word1 = word0 + 8 * ST_W;
        split_pack(x0, y0, hp, lp);
        A_HI[word0] = hp; A_LO[word0] = lp;
        split_pack(x1, y1, hp, lp);
        A_HI[word1] = hp; A_LO[word1] = lp;
#pragma unroll
        for (int j = 0; j < 4; j++) acc[nt][j] = 0.f;
    }

    // ---- stage W2 ----
    {
        const uint4* s2h = reinterpret_cast<const uint4*>(g_w2hi);
        const uint4* s2l = reinterpret_cast<const uint4*>(g_w2lo);
        uint4* dh = reinterpret_cast<uint4*>(W_HI);
        uint4* dl = reinterpret_cast<uint4*>(W_LO);
        for (int i = tid; i < W_WORDS / 4; i += 512) { dh[i] = s2h[i]; dl[i] = s2l[i]; }
    }
    __syncthreads();

    // ================= GEMM 2 =================
#pragma unroll
    for (int kc = 0; kc < 8; kc++) {
        const int kw = kc * 8 + t;
        uint32_t ah[4], al[4];
        ah[0] = A_HI[ar0 + kw];     ah[1] = A_HI[ar1 + kw];
        ah[2] = A_HI[ar0 + kw + 4]; ah[3] = A_HI[ar1 + kw + 4];
        al[0] = A_LO[ar0 + kw];     al[1] = A_LO[ar1 + kw];
        al[2] = A_LO[ar0 + kw + 4]; al[3] = A_LO[ar1 + kw + 4];
#pragma unroll
        for (int nt = 0; nt < 4; nt++) {
            const int bb = (q * 32 + nt * 8 + g) * ST_W + kw;
            uint32_t bh[2] = { W_HI[bb], W_HI[bb + 4] };
            uint32_t bl[2] = { W_LO[bb], W_LO[bb + 4] };
            mma_bf16(acc[nt], ah, bh);
            mma_bf16(acc[nt], ah, bl);
            mma_bf16(acc[nt], al, bh);
        }
    }

    // ---- epilogue 2: +b2, store ----
    {
        const int m0 = row_base + wr * 16 + g;
        const int m1 = m0 + 8;
#pragma unroll
        for (int nt = 0; nt < 4; nt++) {
            const int n = q * 32 + nt * 8 + 2 * t;
            const float bx = __ldg(b2 + n);
            const float by = __ldg(b2 + n + 1);
            if (m0 < N_NODES)
                *reinterpret_cast<float2*>(out + (size_t)m0 * D + n) =
                    make_float2(acc[nt][0] + bx, acc[nt][1] + by);
            if (m1 < N_NODES)
                *reinterpret_cast<float2*>(out + (size_t)m1 * D + n) =
                    make_float2(acc[nt][2] + bx, acc[nt][3] + by);
        }
    }
}

// ---------------------------------------------------------------------------
extern "C" void kernel_launch(void* const* d_in, const int* in_sizes, int n_in,
                              void* d_out, int out_size) {
    const float* feat = (const float*)d_in[0];
    const int*   src  = (const int*)d_in[1];
    const int*   dst  = (const int*)d_in[2];
    const float* eps  = (const float*)d_in[3];
    const float* W1   = (const float*)d_in[4];
    const float* b1   = (const float*)d_in[5];
    const float* W2   = (const float*)d_in[6];
    const float* b2   = (const float*)d_in[7];
    float*       out  = (float*)d_out;

    int n_edges = in_sizes[1];
    int eblocks = (n_edges + 255) / 256;

    // ---- binning (CSR by dst) ----
    zero_cnt_kernel<<<(N_NODES + 255) / 256, 256>>>();
    hist_kernel<<<eblocks, 256>>>(dst, n_edges);
    scan_block_kernel<<<N_SCAN_BLKS, SCAN_BLK>>>();
    scan_top_kernel<<<1, 128>>>();
    scan_final_kernel<<<N_SCAN_BLKS, SCAN_BLK>>>();
    fill_kernel<<<eblocks, 256>>>(src, dst, n_edges);

    // ---- gather-reduce (includes (1+eps)*feat self term) ----
    gather_kernel<<<(N_NODES * 32 + 255) / 256, 256>>>(feat, eps);

    // ---- weights + MLP ----
    prep_weights_kernel<<<(D * D + 255) / 256, 256>>>(W1, W2);
    cudaFuncSetAttribute(mlp_kernel, cudaFuncAttributeMaxDynamicSharedMemorySize,
                         MLP_SMEM_BYTES);
    int blocks = (N_NODES + TILE_M - 1) / TILE_M;
    mlp_kernel<<<blocks, 512, MLP_SMEM_BYTES>>>(b1, b2, out);
}

// round 8
// speedup vs baseline: 1.2391x; 1.0880x over previous
#include <cuda_runtime.h>
#include <cuda_bf16.h>
#include <cuda_fp16.h>
#include <cstdint>

#define N_NODES 100000
#define N_EDGES_MAX 3200000
#define D 128

// ---------------------------------------------------------------------------
// Device scratch (static; no runtime alloc)
// ---------------------------------------------------------------------------
__device__ float g_neigh[(size_t)N_NODES * D];   // (1+eps)feat + neighbor sum
__device__ __align__(16) __half g_featH[(size_t)N_NODES * D];   // fp16 feat image
__device__ int g_cnt[N_NODES];
__device__ int g_off[N_NODES + 1];
__device__ int g_cur[N_NODES];
__device__ int g_srcs[N_EDGES_MAX];
__device__ int g_blksum[128];
__device__ int g_blkoff[128];

// Transposed, padded, split-bf16 weight images: Wt[n][k], row stride 136 elems.
#define ST_ELEM 136
#define ST_W    68
__device__ __align__(16) uint16_t g_w1hi[D * ST_ELEM];
__device__ __align__(16) uint16_t g_w1lo[D * ST_ELEM];
__device__ __align__(16) uint16_t g_w2hi[D * ST_ELEM];
__device__ __align__(16) uint16_t g_w2lo[D * ST_ELEM];

#define SCAN_BLK 1024
#define N_SCAN_BLKS ((N_NODES + SCAN_BLK - 1) / SCAN_BLK)   // 98

// ---------------------------------------------------------------------------
// helpers
// ---------------------------------------------------------------------------
__device__ __forceinline__ void mma_bf16(float* c, const uint32_t* a, const uint32_t* b) {
    asm volatile(
        "mma.sync.aligned.m16n8k16.row.col.f32.bf16.bf16.f32 "
        "{%0,%1,%2,%3}, {%4,%5,%6,%7}, {%8,%9}, {%0,%1,%2,%3};"
        : "+f"(c[0]), "+f"(c[1]), "+f"(c[2]), "+f"(c[3])
        : "r"(a[0]), "r"(a[1]), "r"(a[2]), "r"(a[3]), "r"(b[0]), "r"(b[1]));
}

__device__ __forceinline__ void split_pack(float x, float y, uint32_t& hp, uint32_t& lp) {
    __nv_bfloat16 xh = __float2bfloat16_rn(x);
    __nv_bfloat16 yh = __float2bfloat16_rn(y);
    __nv_bfloat16 xl = __float2bfloat16_rn(x - __bfloat162float(xh));
    __nv_bfloat16 yl = __float2bfloat16_rn(y - __bfloat162float(yh));
    hp = (uint32_t)__bfloat16_as_ushort(xh) | ((uint32_t)__bfloat16_as_ushort(yh) << 16);
    lp = (uint32_t)__bfloat16_as_ushort(xl) | ((uint32_t)__bfloat16_as_ushort(yl) << 16);
}

// ---------------------------------------------------------------------------
// Binning pipeline
// ---------------------------------------------------------------------------
__global__ void zero_cnt_kernel() {
    int i = blockIdx.x * blockDim.x + threadIdx.x;
    if (i < N_NODES) g_cnt[i] = 0;
}

__global__ void hist_kernel(const int* __restrict__ dst, int n_edges) {
    int i = blockIdx.x * blockDim.x + threadIdx.x;
    if (i < n_edges) atomicAdd(&g_cnt[dst[i]], 1);
}

__global__ void scan_block_kernel() {
    __shared__ int s[SCAN_BLK];
    int t = threadIdx.x;
    int i = blockIdx.x * SCAN_BLK + t;
    s[t] = (i < N_NODES) ? g_cnt[i] : 0;
    __syncthreads();
    for (int off = SCAN_BLK / 2; off > 0; off >>= 1) {
        if (t < off) s[t] += s[t + off];
        __syncthreads();
    }
    if (t == 0) g_blksum[blockIdx.x] = s[0];
}

__global__ void scan_top_kernel() {
    __shared__ int s[128];
    int t = threadIdx.x;
    int v = (t < N_SCAN_BLKS) ? g_blksum[t] : 0;
    s[t] = v;
    __syncthreads();
#pragma unroll
    for (int off = 1; off < 128; off <<= 1) {
        int x = (t >= off) ? s[t - off] : 0;
        __syncthreads();
        s[t] += x;
        __syncthreads();
    }
    if (t < N_SCAN_BLKS) g_blkoff[t] = s[t] - v;
    if (t == N_SCAN_BLKS - 1) g_off[N_NODES] = s[t];
}

__global__ void scan_final_kernel() {
    __shared__ int s[SCAN_BLK];
    int t = threadIdx.x;
    int i = blockIdx.x * SCAN_BLK + t;
    int v = (i < N_NODES) ? g_cnt[i] : 0;
    s[t] = v;
    __syncthreads();
    for (int off = 1; off < SCAN_BLK; off <<= 1) {
        int x = (t >= off) ? s[t - off] : 0;
        __syncthreads();
        s[t] += x;
        __syncthreads();
    }
    if (i < N_NODES) {
        int excl = s[t] - v + g_blkoff[blockIdx.x];
        g_off[i] = excl;
        g_cur[i] = excl;
    }
}

__global__ void fill_kernel(const int* __restrict__ src,
                            const int* __restrict__ dst, int n_edges) {
    int i = blockIdx.x * blockDim.x + threadIdx.x;
    if (i < n_edges) {
        int pos = atomicAdd(&g_cur[dst[i]], 1);
        g_srcs[pos] = src[i];
    }
}

// ---------------------------------------------------------------------------
// feat -> fp16 image (messages only; self term stays fp32)
// ---------------------------------------------------------------------------
__global__ void feat2half_kernel(const float* __restrict__ feat) {
    size_t total8 = (size_t)N_NODES * D / 8;
    size_t stride = (size_t)gridDim.x * blockDim.x;
    for (size_t i = (size_t)blockIdx.x * blockDim.x + threadIdx.x; i < total8; i += stride) {
        float4 a = reinterpret_cast<const float4*>(feat)[2 * i];
        float4 b = reinterpret_cast<const float4*>(feat)[2 * i + 1];
        __half2 h[4];
        h[0] = __floats2half2_rn(a.x, a.y);
        h[1] = __floats2half2_rn(a.z, a.w);
        h[2] = __floats2half2_rn(b.x, b.y);
        h[3] = __floats2half2_rn(b.z, b.w);
        reinterpret_cast<uint2*>(g_featH)[2 * i]     = make_uint2(
            *reinterpret_cast<uint32_t*>(&h[0]), *reinterpret_cast<uint32_t*>(&h[1]));
        reinterpret_cast<uint2*>(g_featH)[2 * i + 1] = make_uint2(
            *reinterpret_cast<uint32_t*>(&h[2]), *reinterpret_cast<uint32_t*>(&h[3]));
    }
}

// ---------------------------------------------------------------------------
// Gather-reduce: warp per node, fp16 messages, fp32 accumulate.
// g_neigh[v] = (1+eps)*feat[v] (fp32) + sum g_featH[srcs] (fp16->fp32)
// Each lane owns 4 columns: one uint2 (4 halves) per neighbor row.
// ---------------------------------------------------------------------------
__global__ __launch_bounds__(256)
void gather_kernel(const float* __restrict__ feat,
                   const float* __restrict__ epsp) {
    const int warp = (blockIdx.x * blockDim.x + threadIdx.x) >> 5;
    const int lane = threadIdx.x & 31;
    if (warp >= N_NODES) return;
    const int v = warp;
    const float e1 = 1.0f + epsp[0];

    const float4* f4 = reinterpret_cast<const float4*>(feat);
    const uint2*  fh = reinterpret_cast<const uint2*>(g_featH);   // 4 halves per uint2

    float4 a = f4[(size_t)v * 32 + lane];
    float4 acc = make_float4(a.x * e1, a.y * e1, a.z * e1, a.w * e1);

    const int beg = g_off[v];
    const int end = g_off[v + 1];
    for (int e = beg; e < end; e += 32) {
        int cnt = end - e;
        if (cnt > 32) cnt = 32;
        int s = (lane < cnt) ? g_srcs[e + lane] : 0;
        if (cnt == 32) {
#pragma unroll
            for (int j = 0; j < 32; j++) {
                int sj = __shfl_sync(0xffffffffu, s, j);
                uint2 m = fh[(size_t)sj * 32 + lane];
                float2 f0 = __half22float2(*reinterpret_cast<__half2*>(&m.x));
                float2 f1 = __half22float2(*reinterpret_cast<__half2*>(&m.y));
                acc.x += f0.x; acc.y += f0.y; acc.z += f1.x; acc.w += f1.y;
            }
        } else {
            for (int j = 0; j < cnt; j++) {
                int sj = __shfl_sync(0xffffffffu, s, j);
                uint2 m = fh[(size_t)sj * 32 + lane];
                float2 f0 = __half22float2(*reinterpret_cast<__half2*>(&m.x));
                float2 f1 = __half22float2(*reinterpret_cast<__half2*>(&m.y));
                acc.x += f0.x; acc.y += f0.y; acc.z += f1.x; acc.w += f1.y;
            }
        }
    }
    reinterpret_cast<float4*>(g_neigh)[(size_t)v * 32 + lane] = acc;
}

// ---------------------------------------------------------------------------
// Weight prep: Wt[n][k] = W[k][n], split bf16 hi/lo, stride 136
// ---------------------------------------------------------------------------
__global__ void prep_weights_kernel(const float* __restrict__ W1,
                                    const float* __restrict__ W2) {
    int idx = blockIdx.x * blockDim.x + threadIdx.x;
    if (idx >= D * D) return;
    int k = idx >> 7;
    int n = idx & 127;
    int o = n * ST_ELEM + k;
    {
        float w = W1[idx];
        __nv_bfloat16 h = __float2bfloat16_rn(w);
        __nv_bfloat16 l = __float2bfloat16_rn(w - __bfloat162float(h));
        g_w1hi[o] = __bfloat16_as_ushort(h);
        g_w1lo[o] = __bfloat16_as_ushort(l);
    }
    {
        float w = W2[idx];
        __nv_bfloat16 h = __float2bfloat16_rn(w);
        __nv_bfloat16 l = __float2bfloat16_rn(w - __bfloat162float(h));
        g_w2hi[o] = __bfloat16_as_ushort(h);
        g_w2lo[o] = __bfloat16_as_ushort(l);
    }
}

// ---------------------------------------------------------------------------
// MLP (HMMA split-bf16). TILE_M=64 rows, 512 threads / 16 warps, 2 CTAs/SM.
// ---------------------------------------------------------------------------
#define TILE_M   64
#define A_WORDS  (TILE_M * ST_W)       // 4352
#define W_WORDS  (128 * ST_W)          // 8704
#define MLP_SMEM_BYTES ((2 * A_WORDS + 2 * W_WORDS) * 4)   // 104448

__global__ __launch_bounds__(512, 2)
void mlp_kernel(const float* __restrict__ b1,
                const float* __restrict__ b2,
                float* __restrict__ out) {
    extern __shared__ uint32_t smem[];
    uint32_t* A_HI = smem;
    uint32_t* A_LO = smem + A_WORDS;
    uint32_t* W_HI = smem + 2 * A_WORDS;
    uint32_t* W_LO = smem + 2 * A_WORDS + W_WORDS;

    const int tid  = threadIdx.x;
    const int wid  = tid >> 5;
    const int lane = tid & 31;
    const int wr   = wid & 3;
    const int q    = wid >> 2;
    const int g    = lane >> 2;
    const int t    = lane & 3;
    const int row_base = blockIdx.x * TILE_M;

    // ---- stage W1 ----
    {
        const uint4* s1h = reinterpret_cast<const uint4*>(g_w1hi);
        const uint4* s1l = reinterpret_cast<const uint4*>(g_w1lo);
        uint4* dh = reinterpret_cast<uint4*>(W_HI);
        uint4* dl = reinterpret_cast<uint4*>(W_LO);
        for (int i = tid; i < W_WORDS / 4; i += 512) { dh[i] = s1h[i]; dl[i] = s1l[i]; }
    }

    // ---- stage A from g_neigh ----
    for (int i = tid; i < TILE_M * 32; i += 512) {
        int r  = i >> 5;
        int c4 = (i & 31) * 4;
        int m  = row_base + r;
        float4 v = (m < N_NODES)
                 ? *reinterpret_cast<const float4*>(g_neigh + (size_t)m * D + c4)
                 : make_float4(0.f, 0.f, 0.f, 0.f);
        uint32_t h0, l0, h1, l1;
        split_pack(v.x, v.y, h0, l0);
        split_pack(v.z, v.w, h1, l1);
        int word = r * ST_W + (c4 >> 1);
        A_HI[word] = h0; A_HI[word + 1] = h1;
        A_LO[word] = l0; A_LO[word + 1] = l1;
    }
    __syncthreads();

    float acc[4][4];
#pragma unroll
    for (int nt = 0; nt < 4; nt++)
#pragma unroll
        for (int j = 0; j < 4; j++) acc[nt][j] = 0.f;

    const int ar0 = (wr * 16 + g) * ST_W;
    const int ar1 = ar0 + 8 * ST_W;

    // ================= GEMM 1 =================
#pragma unroll
    for (int kc = 0; kc < 8; kc++) {
        const int kw = kc * 8 + t;
        uint32_t ah[4], al[4];
        ah[0] = A_HI[ar0 + kw];     ah[1] = A_HI[ar1 + kw];
        ah[2] = A_HI[ar0 + kw + 4]; ah[3] = A_HI[ar1 + kw + 4];
        al[0] = A_LO[ar0 + kw];     al[1] = A_LO[ar1 + kw];
        al[2] = A_LO[ar0 + kw + 4]; al[3] = A_LO[ar1 + kw + 4];
#pragma unroll
        for (int nt = 0; nt < 4; nt++) {
            const int bb = (q * 32 + nt * 8 + g) * ST_W + kw;
            uint32_t bh[2] = { W_HI[bb], W_HI[bb + 4] };
            uint32_t bl[2] = { W_LO[bb], W_LO[bb + 4] };
            mma_bf16(acc[nt], ah, bh);
            mma_bf16(acc[nt], ah, bl);
            mma_bf16(acc[nt], al, bh);
        }
    }
    __syncthreads();

    // ---- epilogue 1: relu(+b1) -> back into A tiles ----
#pragma unroll
    for (int nt = 0; nt < 4; nt++) {
        const int n = q * 32 + nt * 8 + 2 * t;
        const float bx = __ldg(b1 + n);
        const float by = __ldg(b1 + n + 1);
        float x0 = fmaxf(acc[nt][0] + bx, 0.f);
        float y0 = fmaxf(acc[nt][1] + by, 0.f);
        float x1 = fmaxf(acc[nt][2] + bx, 0.f);
        float y1 = fmaxf(acc[nt][3] + by, 0.f);
        uint32_t hp, lp;
        const int word0 = (wr * 16 + g) * ST_W + (n >> 1);
        const int word1 = word0 + 8 * ST_W;
        split_pack(x0, y0, hp, lp);
        A_HI[word0] = hp; A_LO[word0] = lp;
        split_pack(x1, y1, hp, lp);
        A_HI[word1] = hp; A_LO[word1] = lp;
#pragma unroll
        for (int j = 0; j < 4; j++) acc[nt][j] = 0.f;
    }

    // ---- stage W2 ----
    {
        const uint4* s2h = reinterpret_cast<const uint4*>(g_w2hi);
        const uint4* s2l = reinterpret_cast<const uint4*>(g_w2lo);
        uint4* dh = reinterpret_cast<uint4*>(W_HI);
        uint4* dl = reinterpret_cast<uint4*>(W_LO);
        for (int i = tid; i < W_WORDS / 4; i += 512) { dh[i] = s2h[i]; dl[i] = s2l[i]; }
    }
    __syncthreads();

    // ================= GEMM 2 =================
#pragma unroll
    for (int kc = 0; kc < 8; kc++) {
        const int kw = kc * 8 + t;
        uint32_t ah[4], al[4];
        ah[0] = A_HI[ar0 + kw];     ah[1] = A_HI[ar1 + kw];
        ah[2] = A_HI[ar0 + kw + 4]; ah[3] = A_HI[ar1 + kw + 4];
        al[0] = A_LO[ar0 + kw];     al[1] = A_LO[ar1 + kw];
        al[2] = A_LO[ar0 + kw + 4]; al[3] = A_LO[ar1 + kw + 4];
#pragma unroll
        for (int nt = 0; nt < 4; nt++) {
            const int bb = (q * 32 + nt * 8 + g) * ST_W + kw;
            uint32_t bh[2] = { W_HI[bb], W_HI[bb + 4] };
            uint32_t bl[2] = { W_LO[bb], W_LO[bb + 4] };
            mma_bf16(acc[nt], ah, bh);
            mma_bf16(acc[nt], ah, bl);
            mma_bf16(acc[nt], al, bh);
        }
    }

    // ---- epilogue 2: +b2, store ----
    {
        const int m0 = row_base + wr * 16 + g;
        const int m1 = m0 + 8;
#pragma unroll
        for (int nt = 0; nt < 4; nt++) {
            const int n = q * 32 + nt * 8 + 2 * t;
            const float bx = __ldg(b2 + n);
            const float by = __ldg(b2 + n + 1);
            if (m0 < N_NODES)
                *reinterpret_cast<float2*>(out + (size_t)m0 * D + n) =
                    make_float2(acc[nt][0] + bx, acc[nt][1] + by);
            if (m1 < N_NODES)
                *reinterpret_cast<float2*>(out + (size_t)m1 * D + n) =
                    make_float2(acc[nt][2] + bx, acc[nt][3] + by);
        }
    }
}

// ---------------------------------------------------------------------------
extern "C" void kernel_launch(void* const* d_in, const int* in_sizes, int n_in,
                              void* d_out, int out_size) {
    const float* feat = (const float*)d_in[0];
    const int*   src  = (const int*)d_in[1];
    const int*   dst  = (const int*)d_in[2];
    const float* eps  = (const float*)d_in[3];
    const float* W1   = (const float*)d_in[4];
    const float* b1   = (const float*)d_in[5];
    const float* W2   = (const float*)d_in[6];
    const float* b2   = (const float*)d_in[7];
    float*       out  = (float*)d_out;

    int n_edges = in_sizes[1];
    int eblocks = (n_edges + 255) / 256;

    // ---- binning (CSR by dst) ----
    zero_cnt_kernel<<<(N_NODES + 255) / 256, 256>>>();
    hist_kernel<<<eblocks, 256>>>(dst, n_edges);
    scan_block_kernel<<<N_SCAN_BLKS, SCAN_BLK>>>();
    scan_top_kernel<<<1, 128>>>();
    scan_final_kernel<<<N_SCAN_BLKS, SCAN_BLK>>>();
    fill_kernel<<<eblocks, 256>>>(src, dst, n_edges);

    // ---- fp16 feat image (independent of binning; overlaps in stream order) ----
    feat2half_kernel<<<4096, 256>>>(feat);

    // ---- gather-reduce (fp16 messages, fp32 self term + accumulate) ----
    gather_kernel<<<(N_NODES * 32 + 255) / 256, 256>>>(feat, eps);

    // ---- weights + MLP ----
    prep_weights_kernel<<<(D * D + 255) / 256, 256>>>(W1, W2);
    cudaFuncSetAttribute(mlp_kernel, cudaFuncAttributeMaxDynamicSharedMemorySize,
                         MLP_SMEM_BYTES);
    int blocks = (N_NODES + TILE_M - 1) / TILE_M;
    mlp_kernel<<<blocks, 512, MLP_SMEM_BYTES>>>(b1, b2, out);
}